// round 2
// baseline (speedup 1.0000x reference)
#include <cuda_runtime.h>

// Hidden layer-2 activations (post-relu), produced by the w3 stage, consumed
// by the fused final stage (last block).
__device__ __align__(16) float g_h2[256];
// Last-block-done ticket. Self-resetting: the last block writes 0 back, so
// every graph replay starts from the same state.
__device__ int g_ticket = 0;

#define RPB 2                       // w3 rows per block
#define NBLK (256 / RPB)            // 128 blocks = one wave

__device__ __forceinline__ float dot4(float4 a, float4 b) {
    return a.x * b.x + a.y * b.y + a.z * b.z + a.w * b.w;
}

__global__ void __launch_bounds__(256, 1)
actor_fused_kernel(const float* __restrict__ x,
                   const float* __restrict__ conv_w, const float* __restrict__ conv_b,
                   const float* __restrict__ w0, const float* __restrict__ b0,
                   const float* __restrict__ w1, const float* __restrict__ b1,
                   const float* __restrict__ w2, const float* __restrict__ b2,
                   const float* __restrict__ w3, const float* __restrict__ b3,
                   const float* __restrict__ w4, const float* __restrict__ b4,
                   float* __restrict__ out) {
    __shared__ __align__(16) float h[2048];
    __shared__ float xs[48];
    __shared__ float red[RPB][8];
    __shared__ int is_last;

    const int tid = threadIdx.x;

    if (tid < 48) xs[tid] = x[tid];
    __syncthreads();

    // ---- Build h[2048] (concat of s0,s1,s2,s3,s4,s5), recomputed per block ----
    // h[   0: 128) = relu(w0*x[0,7] + b0)
    // h[ 128: 256) = relu(w1*x[1,7] + b1)
    // h[ 256: 896) = relu(conv1d(x[2,0:8]))  channel-major [128,5]
    // h[ 896:1536) = relu(conv1d(x[3,0:8]))  channel-major [128,5]
    // h[1536:1920) = relu(conv1d(x[4,0:6]))  channel-major [128,3]
    // h[1920:2048) = w2*x[4,7] + b2          (NO relu)
    if (tid < 128) {
        const int c = tid;
        h[c]        = fmaxf(fmaf(w0[c], xs[7],  b0[c]), 0.0f);
        h[128 + c]  = fmaxf(fmaf(w1[c], xs[15], b1[c]), 0.0f);
        h[1920 + c] =       fmaf(w2[c], xs[39], b2[c]);  // no relu
        const float4 wv = *reinterpret_cast<const float4*>(conv_w + c * 4);
        const float cb = conv_b[c];
        #pragma unroll
        for (int t = 0; t < 5; t++) {
            float s = fmaf(wv.x, xs[16 + t],
                      fmaf(wv.y, xs[17 + t],
                      fmaf(wv.z, xs[18 + t],
                      fmaf(wv.w, xs[19 + t], cb))));
            h[256 + c * 5 + t] = fmaxf(s, 0.0f);
        }
    } else {
        const int c = tid - 128;
        const float4 wv = *reinterpret_cast<const float4*>(conv_w + c * 4);
        const float cb = conv_b[c];
        #pragma unroll
        for (int t = 0; t < 5; t++) {
            float s = fmaf(wv.x, xs[24 + t],
                      fmaf(wv.y, xs[25 + t],
                      fmaf(wv.z, xs[26 + t],
                      fmaf(wv.w, xs[27 + t], cb))));
            h[896 + c * 5 + t] = fmaxf(s, 0.0f);
        }
        #pragma unroll
        for (int t = 0; t < 3; t++) {
            float s = fmaf(wv.x, xs[32 + t],
                      fmaf(wv.y, xs[33 + t],
                      fmaf(wv.z, xs[34 + t],
                      fmaf(wv.w, xs[35 + t], cb))));
            h[1536 + c * 3 + t] = fmaxf(s, 0.0f);
        }
    }
    __syncthreads();

    // ---- RPB rows of relu(w3 @ h + b3): float4 loads, 4 LDG.128 in flight ----
    const int row0 = blockIdx.x * RPB;
    const float4* hv = reinterpret_cast<const float4*>(h);
    const float4 h0 = hv[tid * 2];
    const float4 h1 = hv[tid * 2 + 1];

    const float4* wr0 = reinterpret_cast<const float4*>(w3 + (size_t)row0 * 2048);
    const float4* wr1 = reinterpret_cast<const float4*>(w3 + (size_t)(row0 + 1) * 2048);
    const float4 a0 = wr0[tid * 2], a1 = wr0[tid * 2 + 1];
    const float4 c0 = wr1[tid * 2], c1 = wr1[tid * 2 + 1];

    float p0 = dot4(a0, h0) + dot4(a1, h1);
    float p1 = dot4(c0, h0) + dot4(c1, h1);

    #pragma unroll
    for (int o = 16; o > 0; o >>= 1) {
        p0 += __shfl_down_sync(0xFFFFFFFFu, p0, o);
        p1 += __shfl_down_sync(0xFFFFFFFFu, p1, o);
    }
    if ((tid & 31) == 0) {
        red[0][tid >> 5] = p0;
        red[1][tid >> 5] = p1;
    }
    __syncthreads();
    if (tid < RPB) {
        float s = red[tid][0] + red[tid][1] + red[tid][2] + red[tid][3]
                + red[tid][4] + red[tid][5] + red[tid][6] + red[tid][7];
        g_h2[row0 + tid] = fmaxf(s + b3[row0 + tid], 0.0f);
    }

    // ---- Last-block-done: fuse the final 6x256 GEMV into this kernel ----
    __threadfence();             // make g_h2 rows globally visible
    __syncthreads();             // all warps' work (incl. g_h2 store) done
    if (tid == 0) {
        int t = atomicAdd(&g_ticket, 1);
        is_last = (t == NBLK - 1);
    }
    __syncthreads();

    if (is_last) {
        // out[w] = w4[w,:] @ g_h2 + b4[w], one warp per output row.
        if (tid < 192) {
            const int w = tid >> 5;       // 0..5
            const int lane = tid & 31;
            const float4* wr = reinterpret_cast<const float4*>(w4 + w * 256);
            const float4* gv = reinterpret_cast<const float4*>(g_h2);
            float p = dot4(wr[lane * 2], gv[lane * 2])
                    + dot4(wr[lane * 2 + 1], gv[lane * 2 + 1]);
            #pragma unroll
            for (int o = 16; o > 0; o >>= 1)
                p += __shfl_down_sync(0xFFFFFFFFu, p, o);
            if (lane == 0) out[w] = p + b4[w];
        }
        // Reset ticket for the next graph replay.
        if (tid == 0) g_ticket = 0;
    }
}

extern "C" void kernel_launch(void* const* d_in, const int* in_sizes, int n_in,
                              void* d_out, int out_size) {
    const float* x      = (const float*)d_in[0];
    const float* conv_w = (const float*)d_in[1];
    const float* conv_b = (const float*)d_in[2];
    const float* w0 = (const float*)d_in[3];
    const float* b0 = (const float*)d_in[4];
    const float* w1 = (const float*)d_in[5];
    const float* b1 = (const float*)d_in[6];
    const float* w2 = (const float*)d_in[7];
    const float* b2 = (const float*)d_in[8];
    const float* w3 = (const float*)d_in[9];
    const float* b3 = (const float*)d_in[10];
    const float* w4 = (const float*)d_in[11];
    const float* b4 = (const float*)d_in[12];
    float* out = (float*)d_out;

    actor_fused_kernel<<<NBLK, 256>>>(x, conv_w, conv_b,
                                      w0, b0, w1, b1, w2, b2, w3, b3,
                                      w4, b4, out);
}